// round 17
// baseline (speedup 1.0000x reference)
#include <cuda_runtime.h>
#include <cuda_fp16.h>
#include <math_constants.h>
#include <cstdint>

#define NROWS 16384
#define DIM   256
#define KCB   8192
#define MT    64                 /* rows per CTA           */
#define MTILES (NROWS / MT)      /* 256 CTAs               */
#define NTILES (KCB / 128)       /* 64 code tiles          */
#define NHALF  (2 * NTILES)      /* 128 k128xn128 halves   */

/* preprocess block ranges (cb-side only; A handled by GEMM prologue) */
#define PC_BLKS  128             /* split_cb (smem-free)  */
#define PN_BLKS  1024            /* codenorm              */

/* GEMM smem layout (dynamic) */
#define SA_OFF  0                /* A fp16: 4 sub-chunks x 8KB = 32768 */
#define SB_OFF  32768            /* 2 x 32KB B half double buffer      */
#define SCN_OFF 98304            /* 2 x 512B cn tiles / later: cand[64][4] */
#define GEMM_SMEM 99328

/* ------------- device globals (no allocs allowed) ------------- */
__device__ unsigned char g_cbt[NHALF * 32768];       /* 4MB pre-swizzled B fp16 halves*/
__device__ float g_codenorm[KCB];
__device__ float g_losspart[MTILES];
__device__ unsigned g_ctr;

/* ------------- helpers ------------- */
__device__ __forceinline__ unsigned smem_u32(const void* p) {
    unsigned a;
    asm("{ .reg .u64 t; cvta.to.shared.u64 t, %1; cvt.u32.u64 %0, t; }" : "=r"(a) : "l"(p));
    return a;
}
__device__ __forceinline__ void cp_async16(unsigned dst, const void* src) {
    asm volatile("cp.async.cg.shared.global [%0], [%1], 16;" :: "r"(dst), "l"(src) : "memory");
}
/* volatile is load-bearing: keeps smem reads inside their buffer epoch */
__device__ __forceinline__ void ldsm_x4(unsigned* r, unsigned addr) {
    asm volatile("ldmatrix.sync.aligned.m8n8.x4.shared.b16 {%0,%1,%2,%3}, [%4];"
                 : "=r"(r[0]), "=r"(r[1]), "=r"(r[2]), "=r"(r[3]) : "r"(addr));
}
__device__ __forceinline__ void ldsm_x4_t(unsigned* r, unsigned addr) {
    asm volatile("ldmatrix.sync.aligned.m8n8.x4.trans.shared.b16 {%0,%1,%2,%3}, [%4];"
                 : "=r"(r[0]), "=r"(r[1]), "=r"(r[2]), "=r"(r[3]) : "r"(addr));
}
__device__ __forceinline__ void mma16816(float (&c)[4], const unsigned* a, unsigned b0, unsigned b1) {
    asm volatile("mma.sync.aligned.m16n8k16.row.col.f32.f16.f16.f32 "
                 "{%0,%1,%2,%3}, {%4,%5,%6,%7}, {%8,%9}, {%0,%1,%2,%3};"
                 : "+f"(c[0]), "+f"(c[1]), "+f"(c[2]), "+f"(c[3])
                 : "r"(a[0]), "r"(a[1]), "r"(a[2]), "r"(a[3]), "r"(b0), "r"(b1));
}
__device__ __forceinline__ void top2_update(float& v1, int& i1, float& v2, int& i2, float d, int c) {
    if (d < v2) {
        if (d < v1) { v2 = v1; i2 = i1; v1 = d; i1 = c; }
        else        { v2 = d;  i2 = c; }
    }
}
__device__ __forceinline__ void ins4(float (&cv)[4], int (&ci)[4], float v, int i) {
#pragma unroll
    for (int j = 0; j < 4; j++) {
        bool lt = (v < cv[j]) || (v == cv[j] && i < ci[j]);
        float tv = lt ? cv[j] : v; int ti = lt ? ci[j] : i;
        if (lt) { cv[j] = v; ci[j] = i; }
        v = tv; i = ti;
    }
}

/* ---------- K0 (preprocess, smem-free): split_cb | codenorm ---------- */
__global__ void preprocess_kernel(const float* __restrict__ cb) {
    const int bid = blockIdx.x;
    const int tid = threadIdx.x;

    if (bid == 0 && tid == 0) g_ctr = 0;   /* reset GEMM completion counter */

    if (bid < PC_BLKS) {
        /* ---- split_cb: register-only 8x8 transpose, no smem ---- */
        const int hidx = bid;                  /* 0..127 */
        const int nt = hidx >> 1, h = hidx & 1;
        const int bn = tid & 15, bk = tid >> 4;
        const float* src = cb + (size_t)(nt * 128 + bn * 8) * DIM + h * 128 + bk * 8;
        unsigned char* dst = g_cbt + (size_t)hidx * 32768;
        unsigned short hv[8][8];               /* [kk][r] */
#pragma unroll
        for (int r = 0; r < 8; r++) {
            float4 f0 = __ldg((const float4*)(src + (size_t)r * DIM));
            float4 f1 = __ldg((const float4*)(src + (size_t)r * DIM + 4));
            hv[0][r] = __half_as_ushort(__float2half_rn(f0.x));
            hv[1][r] = __half_as_ushort(__float2half_rn(f0.y));
            hv[2][r] = __half_as_ushort(__float2half_rn(f0.z));
            hv[3][r] = __half_as_ushort(__float2half_rn(f0.w));
            hv[4][r] = __half_as_ushort(__float2half_rn(f1.x));
            hv[5][r] = __half_as_ushort(__float2half_rn(f1.y));
            hv[6][r] = __half_as_ushort(__float2half_rn(f1.z));
            hv[7][r] = __half_as_ushort(__float2half_rn(f1.w));
        }
#pragma unroll
        for (int kk = 0; kk < 8; kk++) {
            int k = bk * 8 + kk;
            *(uint4*)(dst + (size_t)k * 256 + ((bn ^ (k & 7)) << 4)) = *(uint4*)hv[kk];
        }
    } else {
        /* ---- codenorm: exact fp32 ||e||^2, one warp per row ---- */
        const int warp = tid >> 5, lane = tid & 31;
        const int row = (bid - PC_BLKS) * 8 + warp;
        const float4* c4 = (const float4*)(cb + (size_t)row * DIM);
        float s = 0.f;
#pragma unroll
        for (int l = 0; l < 2; l++) {
            float4 v = c4[lane + 32 * l];
            s += v.x * v.x + v.y * v.y + v.z * v.z + v.w * v.w;
        }
#pragma unroll
        for (int o = 16; o > 0; o >>= 1) s += __shfl_down_sync(0xffffffffu, s, o);
        if (lane == 0) g_codenorm[row] = s;
    }
}

/* ---------- B-half producer: 32KB into buffer (s&1), one commit group ---------- */
__device__ __forceinline__ void issue_half(unsigned smb, int s, int tid) {
    const unsigned char* src = g_cbt + (size_t)s * 32768 + tid * 16;
    unsigned dst = smb + SB_OFF + (s & 1) * 32768 + tid * 16;
#pragma unroll
    for (int i = 0; i < 8; i++) cp_async16(dst + i * 4096, src + (size_t)i * 4096);
    if ((s & 1) == 0 && tid < 32)
        cp_async16(smb + SCN_OFF + ((s >> 1) & 1) * 512 + tid * 16,
                   (const unsigned char*)g_codenorm + (size_t)(s >> 1) * 512 + tid * 16);
    asm volatile("cp.async.commit_group;" ::: "memory");
}

/* ---------- compute one k128 half: 8 k16-steps, warp tile 32m x 32n, buf = H ---------- */
template<int H>
__device__ __forceinline__ void compute_half(float (&acc)[2][4][4], unsigned smb,
                                             int wm, int wn, int lane) {
    const int mlo = wm * 32 + (lane & 15);
    const int mhi = mlo + 16;
    const int klane = lane & 15;
    const int sel = lane >> 4;
    const unsigned alo_base = smb + SA_OFF + mlo * 128;
    const unsigned ahi_base = smb + SA_OFF + mhi * 128;
    const int xlo = mlo & 7, xhi = mhi & 7;
    const int cb0 = wn * 4 + sel;
    const unsigned bb = smb + SB_OFF + H * 32768 + klane * 256;
    const unsigned b0base = bb + (((cb0)     ^ (klane & 7)) << 4);
    const unsigned b1base = bb + (((cb0 + 2) ^ (klane & 7)) << 4);
#pragma unroll
    for (int ks = 0; ks < 8; ks++) {
        const int base_g = H * 16 + ks * 2;        /* compile-time, even */
        const int sub = base_g >> 3;               /* compile-time       */
        unsigned a0[4], a1[4], b0[4], b1[4];
        {
            int kc = (base_g & 7) + sel;           /* stays within 0..7  */
            ldsm_x4(a0, alo_base + sub * 8192 + ((kc ^ xlo) << 4));
            ldsm_x4(a1, ahi_base + sub * 8192 + ((kc ^ xhi) << 4));
        }
        ldsm_x4_t(b0, b0base + ks * 4096);
        ldsm_x4_t(b1, b1base + ks * 4096);
        mma16816(acc[0][0], a0, b0[0], b0[1]);
        mma16816(acc[0][1], a0, b0[2], b0[3]);
        mma16816(acc[0][2], a0, b1[0], b1[1]);
        mma16816(acc[0][3], a0, b1[2], b1[3]);
        mma16816(acc[1][0], a1, b0[0], b0[1]);
        mma16816(acc[1][1], a1, b0[2], b0[3]);
        mma16816(acc[1][2], a1, b1[0], b1[1]);
        mma16816(acc[1][3], a1, b1[2], b1[3]);
    }
}

/* ---------- K1: fp16 tensor GEMM + top-2 argmin + fused exact rescore/gather/loss ---------- */
__global__ void __launch_bounds__(256, 2) vq_mma_kernel(const float* __restrict__ z,
                                                        const float* __restrict__ cb,
                                                        float* __restrict__ out) {
    extern __shared__ __align__(128) unsigned char smem[];
    __shared__ float wsum[8];
    __shared__ float sred[256];
    __shared__ int s_last;
    const unsigned smb = smem_u32(smem);
    const int tid = threadIdx.x;
    const int lane = tid & 31;
    const int w = tid >> 5;
    const int wm = w >> 2, wn = w & 3;
    const int mtile = blockIdx.x;

    /* start B half 0 + cn tile 0 first so the A conversion hides under it */
    issue_half(smb, 0, tid);

    { /* prologue: load fp32 A tile, copy to out_ze, convert+swizzle into SA smem */
        const float* zsrc = z + (size_t)mtile * MT * DIM;
        float* oz = out + (size_t)mtile * MT * DIM;
#pragma unroll
        for (int l = 0; l < 8; l++) {
            const int id = l * 256 + tid;       /* 0..2047 */
            const int m = id >> 5, j = id & 31; /* row, 16B k-chunk */
            const float4* s4 = (const float4*)(zsrc + (size_t)m * DIM + j * 8);
            float4 f0 = __ldg(s4), f1 = __ldg(s4 + 1);
            *(float4*)(oz + (size_t)m * DIM + j * 8)     = f0;
            *(float4*)(oz + (size_t)m * DIM + j * 8 + 4) = f1;
            float v[8] = {f0.x, f0.y, f0.z, f0.w, f1.x, f1.y, f1.z, f1.w};
            unsigned short hv[8];
#pragma unroll
            for (int e = 0; e < 8; e++) hv[e] = __half_as_ushort(__float2half_rn(v[e]));
            const int kc = j >> 3, c = j & 7;
            *(uint4*)(smem + SA_OFF + kc * 8192 + m * 128 + ((c ^ (m & 7)) << 4)) = *(uint4*)hv;
        }
    }

    float acc[2][4][4];
#pragma unroll
    for (int i = 0; i < 2; i++)
#pragma unroll
        for (int j = 0; j < 4; j++)
#pragma unroll
            for (int r = 0; r < 4; r++) acc[i][j][r] = 0.f;
    float tv1[4], tv2[4];
    int ti1[4], ti2[4];
#pragma unroll
    for (int sl = 0; sl < 4; sl++) { tv1[sl] = CUDART_INF_F; tv2[sl] = CUDART_INF_F; ti1[sl] = 0; ti2[sl] = 0; }

    const int colb = wn * 32 + 2 * (lane & 3);
    for (int ii = 0; ii < NTILES; ii++) {
        /* ---- half 0 of tile ii ---- */
        asm volatile("cp.async.wait_group 0;" ::: "memory");
        __syncthreads();                        /* also orders prologue STS */
        issue_half(smb, 2 * ii + 1, tid);
        compute_half<0>(acc, smb, wm, wn, lane);
        /* ---- half 1 of tile ii ---- */
        asm volatile("cp.async.wait_group 0;" ::: "memory");
        __syncthreads();
        if (2 * ii + 2 < NHALF) issue_half(smb, 2 * ii + 2, tid);
        compute_half<1>(acc, smb, wm, wn, lane);
        { /* epilogue: dist + top-2, zero acc */
            const float* cnp = (const float*)(smem + SCN_OFF + (ii & 1) * 512);
#pragma unroll
            for (int ni = 0; ni < 4; ni++) {
                float cn0 = cnp[colb + ni * 8];
                float cn1 = cnp[colb + ni * 8 + 1];
                int c0 = ii * 128 + colb + ni * 8;
#pragma unroll
                for (int mi = 0; mi < 2; mi++) {
#pragma unroll
                    for (int h = 0; h < 2; h++) {
                        int sl = mi * 2 + h;
                        float d0 = fmaf(-2.f, acc[mi][ni][h * 2],     cn0);
                        float d1 = fmaf(-2.f, acc[mi][ni][h * 2 + 1], cn1);
                        top2_update(tv1[sl], ti1[sl], tv2[sl], ti2[sl], d0, c0);
                        top2_update(tv1[sl], ti1[sl], tv2[sl], ti2[sl], d1, c0 + 1);
                        acc[mi][ni][h * 2] = 0.f;
                        acc[mi][ni][h * 2 + 1] = 0.f;
                    }
                }
            }
        }
    }

    /* dump all 32 per-row candidates, then per-row top-4 merge into smem */
    __syncthreads();
    float4* red = (float4*)(smem + SB_OFF);    /* 64 rows x 16 entries x 16B */
#pragma unroll
    for (int sl = 0; sl < 4; sl++) {
        int row = wm * 32 + (sl >> 1) * 16 + (sl & 1) * 8 + (lane >> 2);
        red[row * 16 + wn * 4 + (lane & 3)] =
            make_float4(tv1[sl], __int_as_float(ti1[sl]), tv2[sl], __int_as_float(ti2[sl]));
    }
    __syncthreads();
    if (tid < 64) {
        float cv[4] = {CUDART_INF_F, CUDART_INF_F, CUDART_INF_F, CUDART_INF_F};
        int ci[4] = {0x7fffffff, 0x7fffffff, 0x7fffffff, 0x7fffffff};
#pragma unroll
        for (int e = 0; e < 16; e++) {
            float4 f = red[tid * 16 + e];
            ins4(cv, ci, f.x, __float_as_int(f.y));
            ins4(cv, ci, f.z, __float_as_int(f.w));
        }
        /* cand table reuses the dead codenorm area (64 x int4 = 1KB) */
        *(int4*)(smem + SCN_OFF + tid * 16) = make_int4(ci[0], ci[1], ci[2], ci[3]);
    }
    __syncthreads();

    /* ---- fused exact fp32 rescore + gather z_q + loss partial (warp = 8 rows) ---- */
    float lsum = 0.f;
    const int4* scand = (const int4*)(smem + SCN_OFF);
    for (int rr = 0; rr < 8; rr++) {
        const int r = w * 8 + rr;
        const int4 cd = scand[r];
        const int cand[4] = {cd.x, cd.y, cd.z, cd.w};
        const int grow = mtile * MT + r;
        const float4* zr = (const float4*)(z + (size_t)grow * DIM);
        float4 a0 = __ldg(zr + lane * 2), a1 = __ldg(zr + lane * 2 + 1);
        float4 b[4][2];
        float d[4];
#pragma unroll
        for (int q = 0; q < 4; q++) {
            const float4* e4 = (const float4*)(cb + (size_t)cand[q] * DIM);
            b[q][0] = __ldg(e4 + lane * 2);
            b[q][1] = __ldg(e4 + lane * 2 + 1);
            d[q] = a0.x * b[q][0].x + a0.y * b[q][0].y + a0.z * b[q][0].z + a0.w * b[q][0].w
                 + a1.x * b[q][1].x + a1.y * b[q][1].y + a1.z * b[q][1].z + a1.w * b[q][1].w;
        }
#pragma unroll
        for (int o = 16; o > 0; o >>= 1)
#pragma unroll
            for (int q = 0; q < 4; q++) d[q] += __shfl_xor_sync(0xffffffffu, d[q], o);

        float bv = CUDART_INF_F; int bq = 0, bi = 0x7fffffff;
#pragma unroll
        for (int q = 0; q < 4; q++) {
            float dist = fmaf(-2.f, d[q], __ldg(&g_codenorm[cand[q]]));
            if (dist < bv || (dist == bv && cand[q] < bi)) { bv = dist; bi = cand[q]; bq = q; }
        }
        float* out_zq = out + (size_t)NROWS * DIM + 1 + (size_t)grow * DIM + lane * 8;
        float4 q0 = b[bq][0], q1 = b[bq][1];
        out_zq[0] = q0.x; out_zq[1] = q0.y; out_zq[2] = q0.z; out_zq[3] = q0.w;
        out_zq[4] = q1.x; out_zq[5] = q1.y; out_zq[6] = q1.z; out_zq[7] = q1.w;
        float dx0 = q0.x - a0.x, dy0 = q0.y - a0.y, dz0 = q0.z - a0.z, dw0 = q0.w - a0.w;
        float dx1 = q1.x - a1.x, dy1 = q1.y - a1.y, dz1 = q1.z - a1.z, dw1 = q1.w - a1.w;
        lsum += dx0 * dx0 + dy0 * dy0 + dz0 * dz0 + dw0 * dw0
              + dx1 * dx1 + dy1 * dy1 + dz1 * dz1 + dw1 * dw1;
    }
#pragma unroll
    for (int o = 16; o > 0; o >>= 1) lsum += __shfl_down_sync(0xffffffffu, lsum, o);
    if (lane == 0) wsum[w] = lsum;
    __syncthreads();
    if (tid == 0) {
        float t = 0.f;
#pragma unroll
        for (int wv = 0; wv < 8; wv++) t += wsum[wv];
        g_losspart[mtile] = t;
        __threadfence();
        unsigned r = atomicAdd(&g_ctr, 1u);
        s_last = (r == MTILES - 1) ? 1 : 0;
    }
    __syncthreads();
    if (s_last) {  /* last CTA: deterministic fixed-order final reduce */
        sred[tid] = g_losspart[tid];
        __syncthreads();
        for (int o = 128; o > 0; o >>= 1) {
            if (tid < o) sred[tid] += sred[tid + o];
            __syncthreads();
        }
        if (tid == 0)
            out[(size_t)NROWS * DIM] = 2.f * sred[0] / (float)((size_t)NROWS * DIM);
    }
}

extern "C" void kernel_launch(void* const* d_in, const int* in_sizes, int n_in,
                              void* d_out, int out_size) {
    const float* z  = (const float*)d_in[0];
    const float* cb = (const float*)d_in[1];
    float* out = (float*)d_out;

    cudaFuncSetAttribute(vq_mma_kernel, cudaFuncAttributeMaxDynamicSharedMemorySize, GEMM_SMEM);

    preprocess_kernel<<<PC_BLKS + PN_BLKS, 256>>>(cb);
    vq_mma_kernel<<<MTILES, 256, GEMM_SMEM>>>(z, cb, out);
}